// round 15
// baseline (speedup 1.0000x reference)
#include <cuda_runtime.h>
#include <cuda_fp16.h>
#include <cstdint>

// ---------------------------------------------------------------------------
// Problem constants
// ---------------------------------------------------------------------------
#define HIDDEN   1024
#define FRAMES   16
#define SPATIAL  1024
#define BATCH    2
#define NSEQ     (BATCH*SPATIAL)        // 2048
#define TOKENS   (BATCH*FRAMES*SPATIAL) // 32768
#define NH       16
#define HD       64
#define QKV_N    3072

// ---------------------------------------------------------------------------
// Scratch
// ---------------------------------------------------------------------------
__device__ __half g_xh [(size_t)TOKENS * HIDDEN];  // LN'd + transposed, fp16
__device__ __half g_wqh[(size_t)QKV_N  * HIDDEN];  // w_qkv fp16
__device__ __half g_woh[(size_t)HIDDEN * HIDDEN];  // w_out fp16
__device__ __half g_ah [(size_t)TOKENS * HIDDEN];  // attn out fp16, final order
__device__ __half g_qkv[(size_t)TOKENS * QKV_N];   // QKV fp16
__device__ float2 g_rope[FRAMES * 32];             // (cos, sin) per (t, d)

// ---------------------------------------------------------------------------
// PTX helpers
// ---------------------------------------------------------------------------
__device__ __forceinline__ uint32_t smem_u32(const void* p) {
    uint32_t a;
    asm("{ .reg .u64 t; cvta.to.shared.u64 t, %1; cvt.u32.u64 %0, t; }" : "=r"(a) : "l"(p));
    return a;
}
__device__ __forceinline__ void cp16(uint32_t dst, const void* src) {
    asm volatile("cp.async.cg.shared.global [%0], [%1], 16;" :: "r"(dst), "l"(src));
}
#define CP_COMMIT() asm volatile("cp.async.commit_group;" ::: "memory")
#define CP_WAIT1()  asm volatile("cp.async.wait_group 1;" ::: "memory")

__device__ __forceinline__ void ldmx4(uint32_t addr, uint32_t* r) {
    asm volatile("ldmatrix.sync.aligned.m8n8.x4.shared.b16 {%0,%1,%2,%3}, [%4];"
        : "=r"(r[0]), "=r"(r[1]), "=r"(r[2]), "=r"(r[3]) : "r"(addr));
}
// memory-clobber variant (smem written by plain stores)
__device__ __forceinline__ void ldmx4m(uint32_t addr, uint32_t* r) {
    asm volatile("ldmatrix.sync.aligned.m8n8.x4.shared.b16 {%0,%1,%2,%3}, [%4];"
        : "=r"(r[0]), "=r"(r[1]), "=r"(r[2]), "=r"(r[3]) : "r"(addr) : "memory");
}
// transposed variant (V b-frags for P*V)
__device__ __forceinline__ void ldmx4t(uint32_t addr, uint32_t* r) {
    asm volatile("ldmatrix.sync.aligned.m8n8.x4.trans.shared.b16 {%0,%1,%2,%3}, [%4];"
        : "=r"(r[0]), "=r"(r[1]), "=r"(r[2]), "=r"(r[3]) : "r"(addr) : "memory");
}
// non-volatile: pure register op, lets compiler interleave with LDSM
__device__ __forceinline__ void mma_f16(float* d, const uint32_t* a, const uint32_t* b) {
    asm("mma.sync.aligned.m16n8k16.row.col.f32.f16.f16.f32 "
        "{%0,%1,%2,%3},{%4,%5,%6,%7},{%8,%9},{%0,%1,%2,%3};"
        : "+f"(d[0]), "+f"(d[1]), "+f"(d[2]), "+f"(d[3])
        : "r"(a[0]), "r"(a[1]), "r"(a[2]), "r"(a[3]), "r"(b[0]), "r"(b[1]));
}

// byte offset of 16B chunk (r, ch) in a [rows x 128B] tile, SW128 swizzle
__device__ __forceinline__ uint32_t toff(int r, int ch) {
    return (uint32_t)(r * 128 + ((ch ^ (r & 7)) << 4));
}

// ---------------------------------------------------------------------------
// Kernel 1: LayerNorm + temporal transpose -> fp16
// ---------------------------------------------------------------------------
__global__ __launch_bounds__(256) void ln_transpose_kernel(
    const float* __restrict__ x,
    const float* __restrict__ gamma,
    const float* __restrict__ beta)
{
    const int token = blockIdx.x;
    const int b  = token >> 14;
    const int sg = token & 16383;
    const int t  = sg >> 10;
    const int s  = sg & 1023;

    const int tid = threadIdx.x;
    const float4 v = ((const float4*)(x + (size_t)token * HIDDEN))[tid];

    float sum = v.x + v.y + v.z + v.w;
    float sq  = v.x*v.x + v.y*v.y + v.z*v.z + v.w*v.w;

    #pragma unroll
    for (int o = 16; o > 0; o >>= 1) {
        sum += __shfl_xor_sync(0xffffffffu, sum, o);
        sq  += __shfl_xor_sync(0xffffffffu, sq,  o);
    }
    __shared__ float s_sum[8], s_sq[8];
    __shared__ float s_mu, s_rstd;
    if ((tid & 31) == 0) { s_sum[tid >> 5] = sum; s_sq[tid >> 5] = sq; }
    __syncthreads();
    if (tid == 0) {
        float ts = 0.f, tq = 0.f;
        #pragma unroll
        for (int i = 0; i < 8; ++i) { ts += s_sum[i]; tq += s_sq[i]; }
        const float mu  = ts * (1.0f / HIDDEN);
        const float var = tq * (1.0f / HIDDEN) - mu * mu;
        s_mu = mu;
        s_rstd = rsqrtf(var + 1e-5f);
    }
    __syncthreads();
    const float mu = s_mu, rs = s_rstd;

    const float4 g  = ((const float4*)gamma)[tid];
    const float4 be = ((const float4*)beta)[tid];
    __half h[4];
    h[0] = __float2half_rn((v.x - mu) * rs * g.x + be.x);
    h[1] = __float2half_rn((v.y - mu) * rs * g.y + be.y);
    h[2] = __float2half_rn((v.z - mu) * rs * g.z + be.z);
    h[3] = __float2half_rn((v.w - mu) * rs * g.w + be.w);

    const size_t orow = (size_t)(b * SPATIAL + s) * FRAMES + t;
    *(uint2*)(g_xh + orow * HIDDEN + 4 * tid) = *(uint2*)h;
}

// ---------------------------------------------------------------------------
// fp32 -> fp16 convert for both weight matrices + RoPE table fill
// ---------------------------------------------------------------------------
#define WQ_TOT (QKV_N * 1024)     // 3145728
#define WO_TOT (HIDDEN * 1024)    // 1048576
__global__ __launch_bounds__(256) void w2h_both_kernel(
    const float* __restrict__ wq, __half* __restrict__ wqh,
    const float* __restrict__ wo, __half* __restrict__ woh)
{
    const int gid = blockIdx.x * 256 + threadIdx.x;

    // RoPE table: 512 entries (t 0..15, d 0..31)
    if (gid < FRAMES * 32) {
        const int t = gid >> 5;
        const int d = gid & 31;
        const float inv = __expf(-(float)d * 0.28782313662425576f);
        float sn, cs;
        __sincosf((float)t * inv, &sn, &cs);
        g_rope[gid] = make_float2(cs, sn);
    }

    const int idx = gid * 4;
    const float* src; __half* dst; int off;
    if (idx < WQ_TOT) { src = wq; dst = wqh; off = idx; }
    else               { src = wo; dst = woh; off = idx - WQ_TOT; }
    const float4 v = *(const float4*)(src + off);
    __half h[4] = { __float2half_rn(v.x), __float2half_rn(v.y),
                    __float2half_rn(v.z), __float2half_rn(v.w) };
    *(uint2*)(dst + off) = *(uint2*)h;
}

// ---------------------------------------------------------------------------
// fp16 mma.sync GEMM (unchanged): BM=128, BN=128, BK=64; 128 thr;
// 3-stage cp.async ring, 2 blocks/SM, cross-chunk fragment prefetch.
// ---------------------------------------------------------------------------
#define KCH 16                    // 1024 / 64
#define A_TILE 16384              // 128 rows * 128B (64 halfs)
#define STG3   32768              // A + B per stage
#define GEMM_SMEM (3 * STG3)      // 98304

template <typename OutT>
__global__ __launch_bounds__(128, 2) void gemm_f16(
    const __half* __restrict__ A,
    const __half* __restrict__ B,
    OutT* __restrict__ C, int N)
{
    extern __shared__ __half smem[];
    const uint32_t base = smem_u32(smem);

    const int tid  = threadIdx.x;
    const int lane = tid & 31;
    const int wid  = tid >> 5;
    const int wm   = wid >> 1;         // 0..1  (64-row slab)
    const int wn   = wid & 1;          // 0..1  (64-col slab)
    const int bm   = blockIdx.y * 128;
    const int bn   = blockIdx.x * 128;

    const int sr  = tid >> 3;          // 0..15
    const int sch = tid & 7;           // 16B chunk within 128B row
    const char* aSrc = (const char*)(A + (size_t)(bm + sr) * HIDDEN) + sch * 16;
    const char* bSrc = (const char*)(B + (size_t)(bn + sr) * HIDDEN) + sch * 16;
    const uint32_t aD = toff(sr, sch);
    const uint32_t bD = A_TILE + toff(sr, sch);

    #define LOAD(c, so_abs)                                                     \
    {                                                                           \
        const int koff = (c) * 128;                                             \
        _Pragma("unroll")                                                       \
        for (int i = 0; i < 8; ++i)                                             \
            cp16((so_abs) + aD + i * 2048, aSrc + (size_t)i * (16 * HIDDEN * 2) + koff); \
        _Pragma("unroll")                                                       \
        for (int i = 0; i < 8; ++i)                                             \
            cp16((so_abs) + bD + i * 2048, bSrc + (size_t)i * (16 * HIDDEN * 2) + koff); \
    }

    const int arb = wm * 64 + (lane & 15);
    const int ae  = lane >> 4;
    const int brb = wn * 64 + (lane & 7) + ((lane >> 4) << 3);
    const int be  = (lane >> 3) & 1;

    float acc[4][8][4];
    #pragma unroll
    for (int i = 0; i < 4; ++i)
        #pragma unroll
        for (int j = 0; j < 8; ++j)
            #pragma unroll
            for (int e = 0; e < 4; ++e) acc[i][j][e] = 0.f;

    uint32_t aq[2][16], bq[2][16];

    #define LDFRAG(buf, so, kk)                                                  \
    {                                                                            \
        _Pragma("unroll")                                                        \
        for (int mi = 0; mi < 4; ++mi)                                           \
            ldmx4((so) + toff(arb + mi * 16, (kk) * 2 + ae), &aq[buf][mi*4]);    \
        _Pragma("unroll")                                                        \
        for (int p = 0; p < 4; ++p)                                              \
            ldmx4((so) + A_TILE + toff(brb + p * 16, (kk) * 2 + be), &bq[buf][p*4]); \
    }

    #define MMAALL(buf)                                                          \
    {                                                                            \
        _Pragma("unroll")                                                        \
        for (int mi = 0; mi < 4; ++mi)                                           \
            _Pragma("unroll")                                                    \
            for (int p = 0; p < 4; ++p) {                                        \
                mma_f16(acc[mi][2*p],   &aq[buf][mi*4], &bq[buf][p*4]);          \
                mma_f16(acc[mi][2*p+1], &aq[buf][mi*4], &bq[buf][p*4+2]);        \
            }                                                                    \
    }

    LOAD(0, base);        CP_COMMIT();
    LOAD(1, base + STG3); CP_COMMIT();
    CP_WAIT1();
    __syncthreads();

    uint32_t so_rd = base;
    uint32_t so_ld = base + 2 * STG3;

    LDFRAG(0, so_rd, 0);

    #pragma unroll 1
    for (int c = 0; c < KCH; ++c) {
        if (c + 2 < KCH) { LOAD(c + 2, so_ld); }
        CP_COMMIT();
        so_ld += STG3; if (so_ld > base + 2 * STG3) so_ld = base;

        LDFRAG(1, so_rd, 1);
        MMAALL(0); LDFRAG(0, so_rd, 2);
        MMAALL(1); LDFRAG(1, so_rd, 3);
        MMAALL(0);
        MMAALL(1);

        so_rd += STG3; if (so_rd > base + 2 * STG3) so_rd = base;

        if (c + 1 < KCH) {
            CP_WAIT1();
            __syncthreads();
            LDFRAG(0, so_rd, 0);
        }
    }
    #undef LOAD
    #undef LDFRAG
    #undef MMAALL

    #pragma unroll
    for (int mi = 0; mi < 4; ++mi) {
        const int row = bm + wm * 64 + mi * 16 + (lane >> 2);
        #pragma unroll
        for (int nj = 0; nj < 8; ++nj) {
            const int col = bn + wn * 64 + nj * 8 + (lane & 3) * 2;
            if (sizeof(OutT) == 4) {
                float* Cf = (float*)C;
                *(float2*)(Cf + (size_t)row * N + col)       = make_float2(acc[mi][nj][0], acc[mi][nj][1]);
                *(float2*)(Cf + (size_t)(row + 8) * N + col) = make_float2(acc[mi][nj][2], acc[mi][nj][3]);
            } else {
                __half* Ch = (__half*)C;
                *(__half2*)(Ch + (size_t)row * N + col)       = __float22half2_rn(make_float2(acc[mi][nj][0], acc[mi][nj][1]));
                *(__half2*)(Ch + (size_t)(row + 8) * N + col) = __float22half2_rn(make_float2(acc[mi][nj][2], acc[mi][nj][3]));
            }
        }
    }
}

// ---------------------------------------------------------------------------
// Kernel 3: MMA-based RoPE + causal attention. One warp per (n, head).
// Full-line Q/K loads with shfl-paired RoPE; V via ldmatrix.trans;
// coalesced output through a bank-padded smem bounce.
// ---------------------------------------------------------------------------
#define AW 8          // warps per attention block
#define OP 72         // output bounce pitch in halfs (144B: 16B-aligned, bank-spread)

__global__ __launch_bounds__(32 * AW) void attn_kernel()
{
    const int wib  = threadIdx.x >> 5;
    const int lane = threadIdx.x & 31;
    const int nb = blockIdx.x * AW + wib;  // 0..32767
    const int n  = nb >> 4;
    const int hh = nb & 15;

    __shared__ __align__(16) __half sQ[AW][FRAMES * HD];   // swizzled 128B rows
    __shared__ __align__(16) __half sK[AW][FRAMES * HD];
    __shared__ __align__(16) __half sV[AW][FRAMES * HD];

    __half* q = sQ[wib];
    __half* k = sK[wib];
    __half* v = sV[wib];

    const __half* gq = g_qkv + (size_t)n * FRAMES * QKV_N + hh * HD;

    // phase 1: full-line loads; RoPE pairing via shfl.xor(4) (lane^4 holds
    // chunk ch^4 of the same row). 4 items/lane: row r = it>>3, chunk ch = it&7.
    #pragma unroll
    for (int i = 0; i < 4; ++i) {
        const int it = lane + 32 * i;
        const int r  = it >> 3;
        const int ch = it & 7;
        const char* rowp = (const char*)(gq + (size_t)r * QKV_N);

        uint4 mq = *(const uint4*)(rowp + ch * 16);
        uint4 mk = *(const uint4*)(rowp + HIDDEN * 2 + ch * 16);
        uint4 mv = *(const uint4*)(rowp + 2 * HIDDEN * 2 + ch * 16);
        *(uint4*)((char*)v + toff(r, ch)) = mv;

        // exchange with partner lane (lane^4): partner holds chunk ch^4
        uint4 pq, pk;
        pq.x = __shfl_xor_sync(0xffffffffu, mq.x, 4);
        pq.y = __shfl_xor_sync(0xffffffffu, mq.y, 4);
        pq.z = __shfl_xor_sync(0xffffffffu, mq.z, 4);
        pq.w = __shfl_xor_sync(0xffffffffu, mq.w, 4);
        pk.x = __shfl_xor_sync(0xffffffffu, mk.x, 4);
        pk.y = __shfl_xor_sync(0xffffffffu, mk.y, 4);
        pk.z = __shfl_xor_sync(0xffffffffu, mk.z, 4);
        pk.w = __shfl_xor_sync(0xffffffffu, mk.w, 4);

        const __half* mqe = (const __half*)&mq; const __half* pqe = (const __half*)&pq;
        const __half* mke = (const __half*)&mk; const __half* pke = (const __half*)&pk;
        uint4 oq, ok;
        __half* oqe = (__half*)&oq; __half* oke = (__half*)&ok;
        const float2* rt = g_rope + r * 32 + (ch & 3) * 8;
        if (ch < 4) {
            // lo half: out = lo*cos - hi*sin
            #pragma unroll
            for (int e = 0; e < 8; ++e) {
                const float2 cs = rt[e];
                oqe[e] = __float2half_rn((__half2float(mqe[e]) * cs.x - __half2float(pqe[e]) * cs.y) * 0.125f);
                oke[e] = __float2half_rn( __half2float(mke[e]) * cs.x - __half2float(pke[e]) * cs.y);
            }
        } else {
            // hi half: out = hi*cos + lo*sin
            #pragma unroll
            for (int e = 0; e < 8; ++e) {
                const float2 cs = rt[e];
                oqe[e] = __float2half_rn((__half2float(mqe[e]) * cs.x + __half2float(pqe[e]) * cs.y) * 0.125f);
                oke[e] = __float2half_rn( __half2float(mke[e]) * cs.x + __half2float(pke[e]) * cs.y);
            }
        }
        *(uint4*)((char*)q + toff(r, ch)) = oq;
        *(uint4*)((char*)k + toff(r, ch)) = ok;
    }
    __syncwarp();

    // S = Q * K^T
    const uint32_t qb = smem_u32(q), kb = smem_u32(k), vb = smem_u32(v);
    const int arb = lane & 15;
    const int ae  = lane >> 4;
    const int brb = (lane & 7) + ((lane >> 4) << 3);
    const int be  = (lane >> 3) & 1;

    float s0[4] = {0.f, 0.f, 0.f, 0.f};    // cols 0-7
    float s1[4] = {0.f, 0.f, 0.f, 0.f};    // cols 8-15
    #pragma unroll
    for (int kg = 0; kg < 4; ++kg) {
        uint32_t aqf[4], bqf[4];
        ldmx4m(qb + toff(arb, kg * 2 + ae), aqf);
        ldmx4m(kb + toff(brb, kg * 2 + be), bqf);
        mma_f16(s0, aqf, bqf);
        mma_f16(s1, aqf, bqf + 2);
    }

    // softmax in c-frag registers
    const int rlo = lane >> 2, rhi = rlo + 8;
    const int c0  = 2 * (lane & 3);
    const int jc[4] = {c0, c0 + 1, c0 + 8, c0 + 9};
    float vlo[4] = {s0[0], s0[1], s1[0], s1[1]};
    float vhi[4] = {s0[2], s0[3], s1[2], s1[3]};

    float mlo = -1e30f, mhi = -1e30f;
    #pragma unroll
    for (int e = 0; e < 4; ++e) {
        if (jc[e] <= rlo) mlo = fmaxf(mlo, vlo[e]);
        if (jc[e] <= rhi) mhi = fmaxf(mhi, vhi[e]);
    }
    mlo = fmaxf(mlo, __shfl_xor_sync(0xffffffffu, mlo, 1));
    mlo = fmaxf(mlo, __shfl_xor_sync(0xffffffffu, mlo, 2));
    mhi = fmaxf(mhi, __shfl_xor_sync(0xffffffffu, mhi, 1));
    mhi = fmaxf(mhi, __shfl_xor_sync(0xffffffffu, mhi, 2));

    float elo[4], ehi[4], slo = 0.f, shi = 0.f;
    #pragma unroll
    for (int e = 0; e < 4; ++e) {
        elo[e] = (jc[e] <= rlo) ? __expf(vlo[e] - mlo) : 0.f;
        ehi[e] = (jc[e] <= rhi) ? __expf(vhi[e] - mhi) : 0.f;
        slo += elo[e]; shi += ehi[e];
    }
    slo += __shfl_xor_sync(0xffffffffu, slo, 1);
    slo += __shfl_xor_sync(0xffffffffu, slo, 2);
    shi += __shfl_xor_sync(0xffffffffu, shi, 1);
    shi += __shfl_xor_sync(0xffffffffu, shi, 2);
    const float ilo = 1.f / slo, ihi = 1.f / shi;

    // pack P into fp16 a-frags
    uint32_t pa[4];
    __half2 h0 = __floats2half2_rn(elo[0] * ilo, elo[1] * ilo);
    __half2 h1 = __floats2half2_rn(ehi[0] * ihi, ehi[1] * ihi);
    __half2 h2 = __floats2half2_rn(elo[2] * ilo, elo[3] * ilo);
    __half2 h3 = __floats2half2_rn(ehi[2] * ihi, ehi[3] * ihi);
    pa[0] = *(uint32_t*)&h0; pa[1] = *(uint32_t*)&h1;
    pa[2] = *(uint32_t*)&h2; pa[3] = *(uint32_t*)&h3;

    // O = P * V via ldmatrix.trans b-frags
    float oc[8][4];
    #pragma unroll
    for (int g = 0; g < 8; ++g)
        #pragma unroll
        for (int e = 0; e < 4; ++e) oc[g][e] = 0.f;

    #pragma unroll
    for (int dg = 0; dg < 4; ++dg) {
        uint32_t vq[4];
        ldmx4t(vb + toff(lane & 15, dg * 2 + (lane >> 4)), vq);
        mma_f16(oc[2 * dg],     pa, vq);
        mma_f16(oc[2 * dg + 1], pa, vq + 2);
    }

    // epilogue: bounce through smem (reuse sQ/sK region as [16][OP] halfs,
    // 144B pitch: rows spread across banks) then coalesced 16B stores.
    __half* so = q;   // 16*72*2 = 2304B < 4096B (sQ+sK contiguous per warp? no —
                      // sQ[wib] alone is 2048B; use q for rows 0..13 region safe?
                      // 2304 > 2048, so span into sK is NOT safe. Use sV instead:
                      // V is fully consumed by the MMAs above.)
    so = v;           // sV[wib]: 2048B... also too small. Use sQ[wib] and sK[wib]
                      // jointly: they are adjacent ONLY within their own arrays.
    // Safe approach: sQ[wib] (2048B) + continuation into sK via explicit split
    // is fragile; instead use pitch 64 halfs (128B) with XOR-swizzled chunk
    // addressing for conflict-free STS/LDS within sQ[wib] alone.
    __syncwarp();
    {
        // store oc as half2 at swizzled (row, chunk) locations:
        // row r, half-index col = g*8 + c0 -> chunk ch = (g*8+c0)>>3 = g, elem = c0
        // STS.32 at toff(r, g) + c0*2. Bank check per (g): addr words =
        // (r*32 + ((g ^ (r&7))*4) + (c0>>1)); for lanes: r = rlo(l)=l>>2 spans 8,
        // xor spreads chunks; within one instruction banks = r*32 mod 32 = 0 ...
        // all rows map to same base bank group + xor offset (g^(r&7))*4 + c:
        // r&7 distinct for 8 rows -> (g^(r&7)) distinct -> 4-word groups distinct ✓
        #pragma unroll
        for (int g = 0; g < 8; ++g) {
            *(__half2*)((char*)so + toff(rlo, g) + c0 * 2) = __floats2half2_rn(oc[g][0], oc[g][1]);
            *(__half2*)((char*)so + toff(rhi, g) + c0 * 2) = __floats2half2_rn(oc[g][2], oc[g][3]);
        }
    }
    __syncwarp();
    // coalesced copy out: 128 x 16B items, swizzled source, linear dest
    const int b = n >> 10;
    const int s = n & 1023;
    #pragma unroll
    for (int i = 0; i < 4; ++i) {
        const int it = lane + 32 * i;
        const int r  = it >> 3;
        const int ch = it & 7;
        uint4 val = *(const uint4*)((const char*)so + toff(r, ch));
        *(uint4*)(g_ah + (size_t)(b * 16384 + r * 1024 + s) * HIDDEN + hh * HD + ch * 8) = val;
    }
}

// ---------------------------------------------------------------------------
// Launch
// ---------------------------------------------------------------------------
extern "C" void kernel_launch(void* const* d_in, const int* in_sizes, int n_in,
                              void* d_out, int out_size)
{
    const float* x      = (const float*)d_in[0];
    const float* w_qkv  = (const float*)d_in[1];
    const float* w_out  = (const float*)d_in[2];
    const float* gamma  = (const float*)d_in[3];
    const float* beta   = (const float*)d_in[4];
    float* out = (float*)d_out;

    __half *xh, *wqh, *woh, *ah, *qkv;
    cudaGetSymbolAddress((void**)&xh,  g_xh);
    cudaGetSymbolAddress((void**)&wqh, g_wqh);
    cudaGetSymbolAddress((void**)&woh, g_woh);
    cudaGetSymbolAddress((void**)&ah,  g_ah);
    cudaGetSymbolAddress((void**)&qkv, g_qkv);

    cudaFuncSetAttribute(gemm_f16<__half>, cudaFuncAttributeMaxDynamicSharedMemorySize, GEMM_SMEM);
    cudaFuncSetAttribute(gemm_f16<float>,  cudaFuncAttributeMaxDynamicSharedMemorySize, GEMM_SMEM);

    // 1. LN + temporal transpose -> fp16
    ln_transpose_kernel<<<TOKENS, 256>>>(x, gamma, beta);

    // 1b. weight conversion + RoPE table (one launch)
    w2h_both_kernel<<<(WQ_TOT + WO_TOT) / 4 / 256, 256>>>(w_qkv, wqh, w_out, woh);

    // 2. QKV projection: fp16 GEMM -> fp16
    {
        dim3 grid(QKV_N / 128, TOKENS / 128);
        gemm_f16<__half><<<grid, 128, GEMM_SMEM>>>(xh, wqh, qkv, QKV_N);
    }

    // 3. MMA-based RoPE + causal attention -> fp16 final order
    attn_kernel<<<NSEQ * NH / AW, 32 * AW>>>();

    // 4. Output projection -> d_out fp32
    {
        dim3 grid(HIDDEN / 128, TOKENS / 128);
        gemm_f16<float><<<grid, 128, GEMM_SMEM>>>(ah, woh, out, HIDDEN);
    }
}

// round 16
// speedup vs baseline: 1.0352x; 1.0352x over previous
#include <cuda_runtime.h>
#include <cuda_fp16.h>
#include <cstdint>

// ---------------------------------------------------------------------------
// Problem constants
// ---------------------------------------------------------------------------
#define HIDDEN   1024
#define FRAMES   16
#define SPATIAL  1024
#define BATCH    2
#define NSEQ     (BATCH*SPATIAL)        // 2048
#define TOKENS   (BATCH*FRAMES*SPATIAL) // 32768
#define NH       16
#define HD       64
#define QKV_N    3072

// ---------------------------------------------------------------------------
// Scratch
// ---------------------------------------------------------------------------
__device__ __half g_xh [(size_t)TOKENS * HIDDEN];  // LN'd + transposed, fp16
__device__ __half g_wqh[(size_t)QKV_N  * HIDDEN];  // w_qkv fp16
__device__ __half g_woh[(size_t)HIDDEN * HIDDEN];  // w_out fp16
__device__ __half g_ah [(size_t)TOKENS * HIDDEN];  // attn out fp16, final order
__device__ __half g_qkv[(size_t)TOKENS * QKV_N];   // QKV fp16
__device__ float2 g_rope[FRAMES * 32];             // (cos, sin) per (t, d)

// ---------------------------------------------------------------------------
// PTX helpers
// ---------------------------------------------------------------------------
__device__ __forceinline__ uint32_t smem_u32(const void* p) {
    uint32_t a;
    asm("{ .reg .u64 t; cvta.to.shared.u64 t, %1; cvt.u32.u64 %0, t; }" : "=r"(a) : "l"(p));
    return a;
}
__device__ __forceinline__ void cp16(uint32_t dst, const void* src) {
    asm volatile("cp.async.cg.shared.global [%0], [%1], 16;" :: "r"(dst), "l"(src));
}
#define CP_COMMIT() asm volatile("cp.async.commit_group;" ::: "memory")
#define CP_WAIT1()  asm volatile("cp.async.wait_group 1;" ::: "memory")

__device__ __forceinline__ void ldmx4(uint32_t addr, uint32_t* r) {
    asm volatile("ldmatrix.sync.aligned.m8n8.x4.shared.b16 {%0,%1,%2,%3}, [%4];"
        : "=r"(r[0]), "=r"(r[1]), "=r"(r[2]), "=r"(r[3]) : "r"(addr));
}
// memory-clobber variant (smem written by plain stores)
__device__ __forceinline__ void ldmx4m(uint32_t addr, uint32_t* r) {
    asm volatile("ldmatrix.sync.aligned.m8n8.x4.shared.b16 {%0,%1,%2,%3}, [%4];"
        : "=r"(r[0]), "=r"(r[1]), "=r"(r[2]), "=r"(r[3]) : "r"(addr) : "memory");
}
// transposed variant (V b-frags for P*V)
__device__ __forceinline__ void ldmx4t(uint32_t addr, uint32_t* r) {
    asm volatile("ldmatrix.sync.aligned.m8n8.x4.trans.shared.b16 {%0,%1,%2,%3}, [%4];"
        : "=r"(r[0]), "=r"(r[1]), "=r"(r[2]), "=r"(r[3]) : "r"(addr) : "memory");
}
// non-volatile: pure register op, lets compiler interleave with LDSM
__device__ __forceinline__ void mma_f16(float* d, const uint32_t* a, const uint32_t* b) {
    asm("mma.sync.aligned.m16n8k16.row.col.f32.f16.f16.f32 "
        "{%0,%1,%2,%3},{%4,%5,%6,%7},{%8,%9},{%0,%1,%2,%3};"
        : "+f"(d[0]), "+f"(d[1]), "+f"(d[2]), "+f"(d[3])
        : "r"(a[0]), "r"(a[1]), "r"(a[2]), "r"(a[3]), "r"(b[0]), "r"(b[1]));
}

// byte offset of 16B chunk (r, ch) in a [rows x 128B] tile, SW128 swizzle
__device__ __forceinline__ uint32_t toff(int r, int ch) {
    return (uint32_t)(r * 128 + ((ch ^ (r & 7)) << 4));
}

// ---------------------------------------------------------------------------
// Kernel 1: LayerNorm + temporal transpose -> fp16
// ---------------------------------------------------------------------------
__global__ __launch_bounds__(256) void ln_transpose_kernel(
    const float* __restrict__ x,
    const float* __restrict__ gamma,
    const float* __restrict__ beta)
{
    const int token = blockIdx.x;
    const int b  = token >> 14;
    const int sg = token & 16383;
    const int t  = sg >> 10;
    const int s  = sg & 1023;

    const int tid = threadIdx.x;
    const float4 v = ((const float4*)(x + (size_t)token * HIDDEN))[tid];

    float sum = v.x + v.y + v.z + v.w;
    float sq  = v.x*v.x + v.y*v.y + v.z*v.z + v.w*v.w;

    #pragma unroll
    for (int o = 16; o > 0; o >>= 1) {
        sum += __shfl_xor_sync(0xffffffffu, sum, o);
        sq  += __shfl_xor_sync(0xffffffffu, sq,  o);
    }
    __shared__ float s_sum[8], s_sq[8];
    __shared__ float s_mu, s_rstd;
    if ((tid & 31) == 0) { s_sum[tid >> 5] = sum; s_sq[tid >> 5] = sq; }
    __syncthreads();
    if (tid == 0) {
        float ts = 0.f, tq = 0.f;
        #pragma unroll
        for (int i = 0; i < 8; ++i) { ts += s_sum[i]; tq += s_sq[i]; }
        const float mu  = ts * (1.0f / HIDDEN);
        const float var = tq * (1.0f / HIDDEN) - mu * mu;
        s_mu = mu;
        s_rstd = rsqrtf(var + 1e-5f);
    }
    __syncthreads();
    const float mu = s_mu, rs = s_rstd;

    const float4 g  = ((const float4*)gamma)[tid];
    const float4 be = ((const float4*)beta)[tid];
    __half h[4];
    h[0] = __float2half_rn((v.x - mu) * rs * g.x + be.x);
    h[1] = __float2half_rn((v.y - mu) * rs * g.y + be.y);
    h[2] = __float2half_rn((v.z - mu) * rs * g.z + be.z);
    h[3] = __float2half_rn((v.w - mu) * rs * g.w + be.w);

    const size_t orow = (size_t)(b * SPATIAL + s) * FRAMES + t;
    *(uint2*)(g_xh + orow * HIDDEN + 4 * tid) = *(uint2*)h;
}

// ---------------------------------------------------------------------------
// fp32 -> fp16 convert for both weight matrices + RoPE table fill
// ---------------------------------------------------------------------------
#define WQ_TOT (QKV_N * 1024)     // 3145728
#define WO_TOT (HIDDEN * 1024)    // 1048576
__global__ __launch_bounds__(256) void w2h_both_kernel(
    const float* __restrict__ wq, __half* __restrict__ wqh,
    const float* __restrict__ wo, __half* __restrict__ woh)
{
    const int gid = blockIdx.x * 256 + threadIdx.x;

    // RoPE table: 512 entries (t 0..15, d 0..31)
    if (gid < FRAMES * 32) {
        const int t = gid >> 5;
        const int d = gid & 31;
        const float inv = __expf(-(float)d * 0.28782313662425576f);
        float sn, cs;
        __sincosf((float)t * inv, &sn, &cs);
        g_rope[gid] = make_float2(cs, sn);
    }

    const int idx = gid * 4;
    const float* src; __half* dst; int off;
    if (idx < WQ_TOT) { src = wq; dst = wqh; off = idx; }
    else               { src = wo; dst = woh; off = idx - WQ_TOT; }
    const float4 v = *(const float4*)(src + off);
    __half h[4] = { __float2half_rn(v.x), __float2half_rn(v.y),
                    __float2half_rn(v.z), __float2half_rn(v.w) };
    *(uint2*)(dst + off) = *(uint2*)h;
}

// ---------------------------------------------------------------------------
// fp16 mma.sync GEMM (unchanged): BM=128, BN=128, BK=64; 128 thr;
// 3-stage cp.async ring, 2 blocks/SM, cross-chunk fragment prefetch.
// ---------------------------------------------------------------------------
#define KCH 16                    // 1024 / 64
#define A_TILE 16384              // 128 rows * 128B (64 halfs)
#define STG3   32768              // A + B per stage
#define GEMM_SMEM (3 * STG3)      // 98304

template <typename OutT>
__global__ __launch_bounds__(128, 2) void gemm_f16(
    const __half* __restrict__ A,
    const __half* __restrict__ B,
    OutT* __restrict__ C, int N)
{
    extern __shared__ __half smem[];
    const uint32_t base = smem_u32(smem);

    const int tid  = threadIdx.x;
    const int lane = tid & 31;
    const int wid  = tid >> 5;
    const int wm   = wid >> 1;         // 0..1  (64-row slab)
    const int wn   = wid & 1;          // 0..1  (64-col slab)
    const int bm   = blockIdx.y * 128;
    const int bn   = blockIdx.x * 128;

    const int sr  = tid >> 3;          // 0..15
    const int sch = tid & 7;           // 16B chunk within 128B row
    const char* aSrc = (const char*)(A + (size_t)(bm + sr) * HIDDEN) + sch * 16;
    const char* bSrc = (const char*)(B + (size_t)(bn + sr) * HIDDEN) + sch * 16;
    const uint32_t aD = toff(sr, sch);
    const uint32_t bD = A_TILE + toff(sr, sch);

    #define LOAD(c, so_abs)                                                     \
    {                                                                           \
        const int koff = (c) * 128;                                             \
        _Pragma("unroll")                                                       \
        for (int i = 0; i < 8; ++i)                                             \
            cp16((so_abs) + aD + i * 2048, aSrc + (size_t)i * (16 * HIDDEN * 2) + koff); \
        _Pragma("unroll")                                                       \
        for (int i = 0; i < 8; ++i)                                             \
            cp16((so_abs) + bD + i * 2048, bSrc + (size_t)i * (16 * HIDDEN * 2) + koff); \
    }

    const int arb = wm * 64 + (lane & 15);
    const int ae  = lane >> 4;
    const int brb = wn * 64 + (lane & 7) + ((lane >> 4) << 3);
    const int be  = (lane >> 3) & 1;

    float acc[4][8][4];
    #pragma unroll
    for (int i = 0; i < 4; ++i)
        #pragma unroll
        for (int j = 0; j < 8; ++j)
            #pragma unroll
            for (int e = 0; e < 4; ++e) acc[i][j][e] = 0.f;

    uint32_t aq[2][16], bq[2][16];

    #define LDFRAG(buf, so, kk)                                                  \
    {                                                                            \
        _Pragma("unroll")                                                        \
        for (int mi = 0; mi < 4; ++mi)                                           \
            ldmx4((so) + toff(arb + mi * 16, (kk) * 2 + ae), &aq[buf][mi*4]);    \
        _Pragma("unroll")                                                        \
        for (int p = 0; p < 4; ++p)                                              \
            ldmx4((so) + A_TILE + toff(brb + p * 16, (kk) * 2 + be), &bq[buf][p*4]); \
    }

    #define MMAALL(buf)                                                          \
    {                                                                            \
        _Pragma("unroll")                                                        \
        for (int mi = 0; mi < 4; ++mi)                                           \
            _Pragma("unroll")                                                    \
            for (int p = 0; p < 4; ++p) {                                        \
                mma_f16(acc[mi][2*p],   &aq[buf][mi*4], &bq[buf][p*4]);          \
                mma_f16(acc[mi][2*p+1], &aq[buf][mi*4], &bq[buf][p*4+2]);        \
            }                                                                    \
    }

    LOAD(0, base);        CP_COMMIT();
    LOAD(1, base + STG3); CP_COMMIT();
    CP_WAIT1();
    __syncthreads();

    uint32_t so_rd = base;
    uint32_t so_ld = base + 2 * STG3;

    LDFRAG(0, so_rd, 0);

    #pragma unroll 1
    for (int c = 0; c < KCH; ++c) {
        if (c + 2 < KCH) { LOAD(c + 2, so_ld); }
        CP_COMMIT();
        so_ld += STG3; if (so_ld > base + 2 * STG3) so_ld = base;

        LDFRAG(1, so_rd, 1);
        MMAALL(0); LDFRAG(0, so_rd, 2);
        MMAALL(1); LDFRAG(1, so_rd, 3);
        MMAALL(0);
        MMAALL(1);

        so_rd += STG3; if (so_rd > base + 2 * STG3) so_rd = base;

        if (c + 1 < KCH) {
            CP_WAIT1();
            __syncthreads();
            LDFRAG(0, so_rd, 0);
        }
    }
    #undef LOAD
    #undef LDFRAG
    #undef MMAALL

    #pragma unroll
    for (int mi = 0; mi < 4; ++mi) {
        const int row = bm + wm * 64 + mi * 16 + (lane >> 2);
        #pragma unroll
        for (int nj = 0; nj < 8; ++nj) {
            const int col = bn + wn * 64 + nj * 8 + (lane & 3) * 2;
            if (sizeof(OutT) == 4) {
                float* Cf = (float*)C;
                *(float2*)(Cf + (size_t)row * N + col)       = make_float2(acc[mi][nj][0], acc[mi][nj][1]);
                *(float2*)(Cf + (size_t)(row + 8) * N + col) = make_float2(acc[mi][nj][2], acc[mi][nj][3]);
            } else {
                __half* Ch = (__half*)C;
                *(__half2*)(Ch + (size_t)row * N + col)       = __float22half2_rn(make_float2(acc[mi][nj][0], acc[mi][nj][1]));
                *(__half2*)(Ch + (size_t)(row + 8) * N + col) = __float22half2_rn(make_float2(acc[mi][nj][2], acc[mi][nj][3]));
            }
        }
    }
}

// ---------------------------------------------------------------------------
// Kernel 3: MMA-based RoPE + causal attention. One warp per (n, head).
// R14 front half (in-thread RoPE pairing, no shfl) + validated smem-bounce
// coalesced epilogue (bounce lives in sV, fully consumed by the O MMAs).
// ---------------------------------------------------------------------------
#define AW 8          // warps per attention block

__global__ __launch_bounds__(32 * AW) void attn_kernel()
{
    const int wib  = threadIdx.x >> 5;
    const int lane = threadIdx.x & 31;
    const int nb = blockIdx.x * AW + wib;  // 0..32767
    const int n  = nb >> 4;
    const int hh = nb & 15;

    __shared__ __align__(16) __half sQ[AW][FRAMES * HD];   // swizzled 128B rows
    __shared__ __align__(16) __half sK[AW][FRAMES * HD];
    __shared__ __align__(16) __half sV[AW][FRAMES * HD];

    __half* q = sQ[wib];
    __half* k = sK[wib];
    __half* v = sV[wib];

    const __half* gq = g_qkv + (size_t)n * FRAMES * QKV_N + hh * HD;

    // phase 1a: Q,K copy with fused RoPE. 64 items: (r, cp) — chunk cp pairs
    // with chunk cp+4 (d and d+32), both loaded by the same thread (no shfl).
    #pragma unroll
    for (int i = 0; i < 2; ++i) {
        const int it = lane + 32 * i;      // 0..63
        const int r  = it >> 2;            // frame
        const int cp = it & 3;             // chunk pair index (d-lo chunk)
        const char* rowp = (const char*)(gq + (size_t)r * QKV_N);

        uint4 qlo = *(const uint4*)(rowp + cp * 16);
        uint4 qhi = *(const uint4*)(rowp + (cp + 4) * 16);
        uint4 klo = *(const uint4*)(rowp + HIDDEN * 2 + cp * 16);
        uint4 khi = *(const uint4*)(rowp + HIDDEN * 2 + (cp + 4) * 16);
        const __half* ql = (const __half*)&qlo; const __half* qh = (const __half*)&qhi;
        const __half* kl = (const __half*)&klo; const __half* kh = (const __half*)&khi;

        uint4 oql, oqh, okl, okh;
        __half* pql = (__half*)&oql; __half* pqh = (__half*)&oqh;
        __half* pkl = (__half*)&okl; __half* pkh = (__half*)&okh;
        const float2* rt = g_rope + r * 32 + cp * 8;
        #pragma unroll
        for (int e = 0; e < 8; ++e) {
            const float2 cs = rt[e];
            const float q1 = __half2float(ql[e]), q2 = __half2float(qh[e]);
            pql[e] = __float2half_rn((q1 * cs.x - q2 * cs.y) * 0.125f);
            pqh[e] = __float2half_rn((q2 * cs.x + q1 * cs.y) * 0.125f);
            const float k1 = __half2float(kl[e]), k2 = __half2float(kh[e]);
            pkl[e] = __float2half_rn(k1 * cs.x - k2 * cs.y);
            pkh[e] = __float2half_rn(k2 * cs.x + k1 * cs.y);
        }
        *(uint4*)((char*)q + toff(r, cp))     = oql;
        *(uint4*)((char*)q + toff(r, cp + 4)) = oqh;
        *(uint4*)((char*)k + toff(r, cp))     = okl;
        *(uint4*)((char*)k + toff(r, cp + 4)) = okh;
    }
    // phase 1b: V plain swizzled copy (consumed via ldmatrix.trans)
    #pragma unroll
    for (int i = 0; i < 4; ++i) {
        const int it = lane + 32 * i;      // 0..127
        const int r  = it >> 3;
        const int ch = it & 7;
        *(uint4*)((char*)v + toff(r, ch)) =
            *(const uint4*)((const char*)(gq + (size_t)r * QKV_N + 2 * HIDDEN) + ch * 16);
    }
    __syncwarp();

    // S = Q * K^T
    const uint32_t qb = smem_u32(q), kb = smem_u32(k), vb = smem_u32(v);
    const int arb = lane & 15;
    const int ae  = lane >> 4;
    const int brb = (lane & 7) + ((lane >> 4) << 3);
    const int be  = (lane >> 3) & 1;

    float s0[4] = {0.f, 0.f, 0.f, 0.f};    // cols 0-7
    float s1[4] = {0.f, 0.f, 0.f, 0.f};    // cols 8-15
    #pragma unroll
    for (int kg = 0; kg < 4; ++kg) {
        uint32_t aqf[4], bqf[4];
        ldmx4m(qb + toff(arb, kg * 2 + ae), aqf);
        ldmx4m(kb + toff(brb, kg * 2 + be), bqf);
        mma_f16(s0, aqf, bqf);
        mma_f16(s1, aqf, bqf + 2);
    }

    // softmax in c-frag registers
    const int rlo = lane >> 2, rhi = rlo + 8;
    const int c0  = 2 * (lane & 3);
    const int jc[4] = {c0, c0 + 1, c0 + 8, c0 + 9};
    float vlo[4] = {s0[0], s0[1], s1[0], s1[1]};
    float vhi[4] = {s0[2], s0[3], s1[2], s1[3]};

    float mlo = -1e30f, mhi = -1e30f;
    #pragma unroll
    for (int e = 0; e < 4; ++e) {
        if (jc[e] <= rlo) mlo = fmaxf(mlo, vlo[e]);
        if (jc[e] <= rhi) mhi = fmaxf(mhi, vhi[e]);
    }
    mlo = fmaxf(mlo, __shfl_xor_sync(0xffffffffu, mlo, 1));
    mlo = fmaxf(mlo, __shfl_xor_sync(0xffffffffu, mlo, 2));
    mhi = fmaxf(mhi, __shfl_xor_sync(0xffffffffu, mhi, 1));
    mhi = fmaxf(mhi, __shfl_xor_sync(0xffffffffu, mhi, 2));

    float elo[4], ehi[4], slo = 0.f, shi = 0.f;
    #pragma unroll
    for (int e = 0; e < 4; ++e) {
        elo[e] = (jc[e] <= rlo) ? __expf(vlo[e] - mlo) : 0.f;
        ehi[e] = (jc[e] <= rhi) ? __expf(vhi[e] - mhi) : 0.f;
        slo += elo[e]; shi += ehi[e];
    }
    slo += __shfl_xor_sync(0xffffffffu, slo, 1);
    slo += __shfl_xor_sync(0xffffffffu, slo, 2);
    shi += __shfl_xor_sync(0xffffffffu, shi, 1);
    shi += __shfl_xor_sync(0xffffffffu, shi, 2);
    const float ilo = 1.f / slo, ihi = 1.f / shi;

    // pack P into fp16 a-frags
    uint32_t pa[4];
    __half2 h0 = __floats2half2_rn(elo[0] * ilo, elo[1] * ilo);
    __half2 h1 = __floats2half2_rn(ehi[0] * ihi, ehi[1] * ihi);
    __half2 h2 = __floats2half2_rn(elo[2] * ilo, elo[3] * ilo);
    __half2 h3 = __floats2half2_rn(ehi[2] * ihi, ehi[3] * ihi);
    pa[0] = *(uint32_t*)&h0; pa[1] = *(uint32_t*)&h1;
    pa[2] = *(uint32_t*)&h2; pa[3] = *(uint32_t*)&h3;

    // O = P * V via ldmatrix.trans b-frags
    float oc[8][4];
    #pragma unroll
    for (int g = 0; g < 8; ++g)
        #pragma unroll
        for (int e = 0; e < 4; ++e) oc[g][e] = 0.f;

    #pragma unroll
    for (int dg = 0; dg < 4; ++dg) {
        uint32_t vq[4];
        ldmx4t(vb + toff(lane & 15, dg * 2 + (lane >> 4)), vq);
        mma_f16(oc[2 * dg],     pa, vq);
        mma_f16(oc[2 * dg + 1], pa, vq + 2);
    }

    // epilogue: bounce through sV (fully consumed above) as a swizzled
    // [16 x 64 half] tile, then coalesced 16B stores.
    __syncwarp();
    #pragma unroll
    for (int g = 0; g < 8; ++g) {
        // STS.32 at toff(r, g) + c0*2 — banks (g^(r&7))*4 + c0/2 distinct
        // across the warp for each g: conflict-free (validated in R15).
        *(__half2*)((char*)v + toff(rlo, g) + c0 * 2) = __floats2half2_rn(oc[g][0], oc[g][1]);
        *(__half2*)((char*)v + toff(rhi, g) + c0 * 2) = __floats2half2_rn(oc[g][2], oc[g][3]);
    }
    __syncwarp();
    const int b = n >> 10;
    const int s = n & 1023;
    #pragma unroll
    for (int i = 0; i < 4; ++i) {
        const int it = lane + 32 * i;
        const int r  = it >> 3;
        const int ch = it & 7;
        uint4 val = *(const uint4*)((const char*)v + toff(r, ch));
        *(uint4*)(g_ah + (size_t)(b * 16384 + r * 1024 + s) * HIDDEN + hh * HD + ch * 8) = val;
    }
}

// ---------------------------------------------------------------------------
// Launch
// ---------------------------------------------------------------------------
extern "C" void kernel_launch(void* const* d_in, const int* in_sizes, int n_in,
                              void* d_out, int out_size)
{
    const float* x      = (const float*)d_in[0];
    const float* w_qkv  = (const float*)d_in[1];
    const float* w_out  = (const float*)d_in[2];
    const float* gamma  = (const float*)d_in[3];
    const float* beta   = (const float*)d_in[4];
    float* out = (float*)d_out;

    __half *xh, *wqh, *woh, *ah, *qkv;
    cudaGetSymbolAddress((void**)&xh,  g_xh);
    cudaGetSymbolAddress((void**)&wqh, g_wqh);
    cudaGetSymbolAddress((void**)&woh, g_woh);
    cudaGetSymbolAddress((void**)&ah,  g_ah);
    cudaGetSymbolAddress((void**)&qkv, g_qkv);

    cudaFuncSetAttribute(gemm_f16<__half>, cudaFuncAttributeMaxDynamicSharedMemorySize, GEMM_SMEM);
    cudaFuncSetAttribute(gemm_f16<float>,  cudaFuncAttributeMaxDynamicSharedMemorySize, GEMM_SMEM);

    // 1. LN + temporal transpose -> fp16
    ln_transpose_kernel<<<TOKENS, 256>>>(x, gamma, beta);

    // 1b. weight conversion + RoPE table (one launch)
    w2h_both_kernel<<<(WQ_TOT + WO_TOT) / 4 / 256, 256>>>(w_qkv, wqh, w_out, woh);

    // 2. QKV projection: fp16 GEMM -> fp16
    {
        dim3 grid(QKV_N / 128, TOKENS / 128);
        gemm_f16<__half><<<grid, 128, GEMM_SMEM>>>(xh, wqh, qkv, QKV_N);
    }

    // 3. MMA-based RoPE + causal attention -> fp16 final order
    attn_kernel<<<NSEQ * NH / AW, 32 * AW>>>();

    // 4. Output projection -> d_out fp32
    {
        dim3 grid(HIDDEN / 128, TOKENS / 128);
        gemm_f16<float><<<grid, 128, GEMM_SMEM>>>(ah, woh, out, HIDDEN);
    }
}